// round 13
// baseline (speedup 1.0000x reference)
#include <cuda_runtime.h>
#include <cstdint>

#define BB    128
#define CC    16
#define TT    2048
#define HH    256
#define NOUT  10
#define NTHR  256
#define KP    136     // k-pairs: 128 (h) + 8 (x)
#define KQ    34      // k-pairs per warp quarter
#define HT_P  10      // ht row pitch (ull), 16B-aligned rows
#define WROW  130     // W row pitch (ull)

#define WP_ULL  (KP * WROW)          // 17680
#define HT_ULL  (KP * HT_P)          // 1360
static const int SMEM_BYTES = (WP_ULL + HT_ULL) * 8 + 4096 * 4;  // 168704

typedef unsigned long long ull;

// ---- persistent device state ----
__device__ float g_xt[TT * BB * CC];           // x transposed to [t][b*c]
__device__ float g_h[2][BB * HH];              // h double buffer
__device__ unsigned g_flag[16 * 32];           // per-group 8 producer flags (128B apart)

__device__ __forceinline__ ull ffma2(ull a, ull b, ull c) {
    ull d;
    asm("fma.rn.f32x2 %0, %1, %2, %3;" : "=l"(d) : "l"(a), "l"(b), "l"(c));
    return d;
}
__device__ __forceinline__ float psum(ull v) {
    return __uint_as_float((unsigned)(v & 0xffffffffu)) +
           __uint_as_float((unsigned)(v >> 32));
}
__device__ __forceinline__ float sigf(float x)  { return 1.f / (1.f + __expf(-x)); }
__device__ __forceinline__ float tanhfa(float x){ return 1.f - 2.f / (__expf(2.f * x) + 1.f); }
__device__ __forceinline__ unsigned ld_acq(const unsigned* p) {
    unsigned v;
    asm volatile("ld.acquire.gpu.global.u32 %0, [%1];" : "=r"(v) : "l"(p) : "memory");
    return v;
}

// ---------------- init: zero h buffer 0, reset flags ----------------
__global__ void init_kernel() {
    int i = blockIdx.x * blockDim.x + threadIdx.x;
    if (i < BB * HH) g_h[0][i] = 0.f;
    if (i < 16 * 32) g_flag[i] = 0u;
}

// ---------------- transpose x: (b*c, T) -> (t, b*c) ----------------
__global__ void trans_kernel(const float* __restrict__ x) {
    __shared__ float tile[32][33];
    const int t0 = blockIdx.x * 32, r0 = blockIdx.y * 32;
    const int tx = threadIdx.x, ty = threadIdx.y;  // 32 x 8
#pragma unroll
    for (int i = 0; i < 32; i += 8)
        tile[ty + i][tx] = x[(size_t)(r0 + ty + i) * TT + t0 + tx];
    __syncthreads();
#pragma unroll
    for (int i = 0; i < 32; i += 8)
        g_xt[(size_t)(t0 + ty + i) * (BB * CC) + r0 + tx] = tile[tx][ty + i];
}

// ---------------- persistent LSTM: 16 groups x 8 blocks ----------------
__global__ void __launch_bounds__(NTHR, 1) lstm_kernel(
    const float* __restrict__ w_ih, const float* __restrict__ w_hh,
    const float* __restrict__ b_ih, const float* __restrict__ b_hh)
{
    extern __shared__ ull sm[];
    ull* wp = sm;                           // [KP][WROW] W tile (u64 chunks)
    ull* ht = sm + WP_ULL;                  // [KP][HT_P] k-paired [kp][b0..7]
    float* gpart = (float*)(ht + HT_ULL);   // [4 kq][8 b][128 g]

    const int tid = threadIdx.x;
    const int bt  = blockIdx.x >> 3;        // 16 batch tiles (sync group)
    const int ut  = blockIdx.x & 7;         // 8 unit tiles
    const int b0  = bt * 8;
    const int u0  = ut * 32;

    // ---- load W tile (once): local g in [0,128): grow = (g>>5)*HH + u0 + (g&31) ----
    for (int q = tid; q < KP * 128; q += NTHR) {
        const int kp = q >> 7, g = q & 127;
        const int grow = (g >> 5) * HH + u0 + (g & 31);
        ull v;
        if (kp < 128) v = *(const ull*)(w_hh + (size_t)grow * HH + 2 * kp);
        else          v = *(const ull*)(w_ih + (size_t)grow * CC + 2 * (kp - 128));
        wp[kp * WROW + g] = v;
    }

    // ---- pointwise thread state: (b,u) cell; biases in regs ----
    const int pb = tid >> 5;                // local batch 0..7
    const int pu = tid & 31;                // local unit 0..31
    float cReg = 0.f;
    const int ub = u0 + pu;
    const float bI = b_ih[ub]          + b_hh[ub];
    const float bF = b_ih[HH + ub]     + b_hh[HH + ub];
    const float bG = b_ih[2*HH + ub]   + b_hh[2*HH + ub];
    const float bO = b_ih[3*HH + ub]   + b_hh[3*HH + ub];

    // ---- GEMM mapping: warp = (kq 0..3, ghalf 0..1); thread = 4b x 4g ----
    const int lane  = tid & 31;
    const int wrp   = tid >> 5;
    const int kq    = wrp >> 1;
    const int ghalf = wrp & 1;
    const int bs    = (lane & 1) * 4;                     // b: bs..bs+3
    const int gi    = (lane >> 1) & 15;
    const int g0    = ghalf * 64 + gi * 4;                // g: g0..g0+3
    const int kp0   = kq * KQ;

    // ---- x prefetch (tid < 64): one u64 = 2 channels of one batch row ----
    const int xc = tid & 7, xb = tid >> 3;
    ull xp = 0;
    if (tid < 64)
        xp = __ldcg((const ull*)(g_xt) + (size_t)(b0 + xb) * 8 + xc);

    for (int s = 0; s < TT; ++s) {
        // ---- commit prefetched x_t; prefetch next step ----
        if (tid < 64) {
            ht[(128 + xc) * HT_P + xb] = xp;
            if (s + 1 < TT)
                xp = __ldcg((const ull*)(g_xt) + (size_t)(s + 1) * (BB * CC / 2) +
                            (size_t)(b0 + xb) * 8 + xc);
        }
        // ---- stage h_prev: 8 rows x 256 = 1024 u64, 4 per thread ----
        if (s == 0) {
#pragma unroll
            for (int i = 0; i < 4; ++i) {
                const int idx = i * NTHR + tid;
                ht[(idx & 127) * HT_P + (idx >> 7)] = 0ull;
            }
        } else {
            const ull* hsrc = (const ull*)g_h[s & 1] + (size_t)b0 * (HH / 2);
#pragma unroll
            for (int i = 0; i < 4; ++i) {
                const int idx = i * NTHR + tid;          // b*128 + kp (coalesced)
                const int b = idx >> 7, kp = idx & 127;
                ht[kp * HT_P + b] = __ldcg(hsrc + idx);
            }
        }
        __syncthreads();

        // ---- GEMM: 4b x 4g x 34 k-pairs, packed f32x2 ----
        ull a00=0,a01=0,a02=0,a03=0, a10=0,a11=0,a12=0,a13=0;
        ull a20=0,a21=0,a22=0,a23=0, a30=0,a31=0,a32=0,a33=0;
        const ull* hp = ht + kp0 * HT_P + bs;
        const ull* wr = wp + kp0 * WROW + g0;
#pragma unroll 2
        for (int kp = 0; kp < KQ; ++kp) {
            const ulonglong2 hA = *(const ulonglong2*)(hp);       // b: bs,bs+1
            const ulonglong2 hB = *(const ulonglong2*)(hp + 2);   // b: bs+2,bs+3
            const ulonglong2 wA = *(const ulonglong2*)(wr);       // g: g0,g0+1
            const ulonglong2 wB = *(const ulonglong2*)(wr + 2);   // g: g0+2,g0+3
            a00 = ffma2(hA.x, wA.x, a00); a01 = ffma2(hA.x, wA.y, a01);
            a02 = ffma2(hA.x, wB.x, a02); a03 = ffma2(hA.x, wB.y, a03);
            a10 = ffma2(hA.y, wA.x, a10); a11 = ffma2(hA.y, wA.y, a11);
            a12 = ffma2(hA.y, wB.x, a12); a13 = ffma2(hA.y, wB.y, a13);
            a20 = ffma2(hB.x, wA.x, a20); a21 = ffma2(hB.x, wA.y, a21);
            a22 = ffma2(hB.x, wB.x, a22); a23 = ffma2(hB.x, wB.y, a23);
            a30 = ffma2(hB.y, wA.x, a30); a31 = ffma2(hB.y, wA.y, a31);
            a32 = ffma2(hB.y, wB.x, a32); a33 = ffma2(hB.y, wB.y, a33);
            hp += HT_P;
            wr += WROW;
        }
        {
            float* gp = gpart + kq * 1024 + bs * 128 + g0;
            *(float4*)(gp)       = make_float4(psum(a00), psum(a01), psum(a02), psum(a03));
            *(float4*)(gp + 128) = make_float4(psum(a10), psum(a11), psum(a12), psum(a13));
            *(float4*)(gp + 256) = make_float4(psum(a20), psum(a21), psum(a22), psum(a23));
            *(float4*)(gp + 384) = make_float4(psum(a30), psum(a31), psum(a32), psum(a33));
        }
        __syncthreads();

        // ---- pointwise: one (b,u) cell per thread ----
        {
            const float* gp = gpart + pb * 128 + pu;
            float iv = bI, fv = bF, gv = bG, ov = bO;
#pragma unroll
            for (int k = 0; k < 4; ++k) {
                iv += gp[k * 1024];
                fv += gp[k * 1024 + 32];
                gv += gp[k * 1024 + 64];
                ov += gp[k * 1024 + 96];
            }
            cReg = sigf(fv) * cReg + sigf(iv) * tanhfa(gv);
            const float h = sigf(ov) * tanhfa(cReg);
            g_h[(s + 1) & 1][(size_t)(b0 + pb) * HH + u0 + pu] = h;
        }

        // ---- group barrier: own-flag release store + single poller over 8 flags ----
        __syncthreads();
        if (tid == 0) {
            unsigned* fl = &g_flag[bt * 32];
            const unsigned tgt = (unsigned)(s + 1);
            asm volatile("st.release.gpu.global.u32 [%0], %1;"
                         :: "l"(fl + ut), "r"(tgt) : "memory");
            unsigned mn;
            do {
                const unsigned f0 = ld_acq(fl + 0), f1 = ld_acq(fl + 1);
                const unsigned f2 = ld_acq(fl + 2), f3 = ld_acq(fl + 3);
                const unsigned f4 = ld_acq(fl + 4), f5 = ld_acq(fl + 5);
                const unsigned f6 = ld_acq(fl + 6), f7 = ld_acq(fl + 7);
                mn = min(min(min(f0, f1), min(f2, f3)),
                         min(min(f4, f5), min(f6, f7)));
            } while (mn < tgt);
        }
        __syncthreads();
    }
}

// ---------------- classifier + log_softmax ----------------
__global__ void head_kernel(const float* __restrict__ w_out,
                            const float* __restrict__ b_out,
                            float* __restrict__ out)
{
    __shared__ float4 ws[NOUT][64];
    __shared__ float bsm[NOUT];
    const int tid = threadIdx.x;
    for (int q = tid; q < NOUT * 64; q += 128)
        ws[q / 64][q & 63] = ((const float4*)w_out)[q];
    if (tid < NOUT) bsm[tid] = b_out[tid];
    __syncthreads();

    const int b     = blockIdx.x * 16 + (tid >> 3);
    const int slice = tid & 7;
    const float4* hr4 = (const float4*)(g_h[0] + (size_t)b * HH) + slice * 8;

    float acc[NOUT];
#pragma unroll
    for (int j = 0; j < NOUT; ++j) acc[j] = 0.f;
#pragma unroll
    for (int k4 = 0; k4 < 8; ++k4) {
        const float4 hv = hr4[k4];
#pragma unroll
        for (int j = 0; j < NOUT; ++j) {
            const float4 wv = ws[j][slice * 8 + k4];
            acc[j] += hv.x * wv.x + hv.y * wv.y + hv.z * wv.z + hv.w * wv.w;
        }
    }
#pragma unroll
    for (int off = 4; off > 0; off >>= 1)
#pragma unroll
        for (int j = 0; j < NOUT; ++j)
            acc[j] += __shfl_down_sync(0xffffffffu, acc[j], off, 8);

    if (slice == 0) {
#pragma unroll
        for (int j = 0; j < NOUT; ++j) acc[j] += bsm[j];
        float m = acc[0];
#pragma unroll
        for (int j = 1; j < NOUT; ++j) m = fmaxf(m, acc[j]);
        float sum = 0.f;
#pragma unroll
        for (int j = 0; j < NOUT; ++j) sum += expf(acc[j] - m);
        const float lse = m + logf(sum);
#pragma unroll
        for (int j = 0; j < NOUT; ++j) out[b * NOUT + j] = acc[j] - lse;
    }
}

extern "C" void kernel_launch(void* const* d_in, const int* in_sizes, int n_in,
                              void* d_out, int out_size) {
    const float* x     = (const float*)d_in[0];
    const float* w_ih  = (const float*)d_in[1];
    const float* w_hh  = (const float*)d_in[2];
    const float* b_ih  = (const float*)d_in[3];
    const float* b_hh  = (const float*)d_in[4];
    const float* w_out = (const float*)d_in[5];
    const float* b_out = (const float*)d_in[6];
    float* out = (float*)d_out;

    cudaFuncSetAttribute(lstm_kernel, cudaFuncAttributeMaxDynamicSharedMemorySize, SMEM_BYTES);

    init_kernel<<<(BB * HH + 255) / 256, 256>>>();
    trans_kernel<<<dim3(TT / 32, (BB * CC) / 32), dim3(32, 8)>>>(x);
    lstm_kernel<<<128, NTHR, SMEM_BYTES>>>(w_ih, w_hh, b_ih, b_hh);
    head_kernel<<<8, 128>>>(w_out, b_out, out);
}

// round 14
// speedup vs baseline: 1.9496x; 1.9496x over previous
#include <cuda_runtime.h>
#include <cstdint>

#define BB    128
#define CC    16
#define TT    2048
#define HH    256
#define NOUT  10
#define NTHR  256
#define KP    136     // k-pairs: 128 (h) + 8 (x)
#define KQ    34      // k-pairs per warp quarter
#define HT_P  10      // ht row pitch (ull), 16B-aligned rows
#define WROW  130     // W row pitch (ull)

#define WP_ULL  (KP * WROW)          // 17680
#define HT_ULL  (KP * HT_P)          // 1360
static const int SMEM_BYTES = (WP_ULL + HT_ULL) * 8 + 4096 * 4;  // 168704

typedef unsigned long long ull;

// ---- persistent device state ----
__device__ float g_xt[TT * BB * CC];           // x transposed to [t][b*c]
__device__ float g_h[2][BB * HH];              // h double buffer
__device__ unsigned g_cnt[16 * 32];            // per-group arrival counters (128B apart)

__device__ __forceinline__ ull ffma2(ull a, ull b, ull c) {
    ull d;
    asm("fma.rn.f32x2 %0, %1, %2, %3;" : "=l"(d) : "l"(a), "l"(b), "l"(c));
    return d;
}
__device__ __forceinline__ float psum(ull v) {
    return __uint_as_float((unsigned)(v & 0xffffffffu)) +
           __uint_as_float((unsigned)(v >> 32));
}
__device__ __forceinline__ float sigf(float x)  { return 1.f / (1.f + __expf(-x)); }
__device__ __forceinline__ float tanhfa(float x){ return 1.f - 2.f / (__expf(2.f * x) + 1.f); }

// ---------------- init: zero h buffer 0, reset barrier state ----------------
__global__ void init_kernel() {
    int i = blockIdx.x * blockDim.x + threadIdx.x;
    if (i < BB * HH) g_h[0][i] = 0.f;
    if (i < 16 * 32) g_cnt[i] = 0u;
}

// ---------------- transpose x: (b*c, T) -> (t, b*c) ----------------
__global__ void trans_kernel(const float* __restrict__ x) {
    __shared__ float tile[32][33];
    const int t0 = blockIdx.x * 32, r0 = blockIdx.y * 32;
    const int tx = threadIdx.x, ty = threadIdx.y;  // 32 x 8
#pragma unroll
    for (int i = 0; i < 32; i += 8)
        tile[ty + i][tx] = x[(size_t)(r0 + ty + i) * TT + t0 + tx];
    __syncthreads();
#pragma unroll
    for (int i = 0; i < 32; i += 8)
        g_xt[(size_t)(t0 + ty + i) * (BB * CC) + r0 + tx] = tile[tx][ty + i];
}

// ---------------- persistent LSTM: 16 groups x 8 blocks ----------------
__global__ void __launch_bounds__(NTHR, 1) lstm_kernel(
    const float* __restrict__ w_ih, const float* __restrict__ w_hh,
    const float* __restrict__ b_ih, const float* __restrict__ b_hh)
{
    extern __shared__ ull sm[];
    ull* wp = sm;                           // [KP][WROW] W tile (u64 chunks)
    ull* ht = sm + WP_ULL;                  // [KP][HT_P] k-paired [kp][b0..7]
    float* gpart = (float*)(ht + HT_ULL);   // [4 kq][8 b][128 g]

    const int tid = threadIdx.x;
    const int bt  = blockIdx.x >> 3;        // 16 batch tiles (sync group)
    const int ut  = blockIdx.x & 7;         // 8 unit tiles
    const int b0  = bt * 8;
    const int u0  = ut * 32;

    // ---- load W tile (once): local g in [0,128): grow = (g>>5)*HH + u0 + (g&31) ----
    for (int q = tid; q < KP * 128; q += NTHR) {
        const int kp = q >> 7, g = q & 127;
        const int grow = (g >> 5) * HH + u0 + (g & 31);
        ull v;
        if (kp < 128) v = *(const ull*)(w_hh + (size_t)grow * HH + 2 * kp);
        else          v = *(const ull*)(w_ih + (size_t)grow * CC + 2 * (kp - 128));
        wp[kp * WROW + g] = v;
    }

    // ---- pointwise thread state: (b,u) cell; biases in regs ----
    const int pb = tid >> 5;                // local batch 0..7
    const int pu = tid & 31;                // local unit 0..31
    float cReg = 0.f;
    const int ub = u0 + pu;
    const float bI = b_ih[ub]          + b_hh[ub];
    const float bF = b_ih[HH + ub]     + b_hh[HH + ub];
    const float bG = b_ih[2*HH + ub]   + b_hh[2*HH + ub];
    const float bO = b_ih[3*HH + ub]   + b_hh[3*HH + ub];

    // ---- GEMM mapping: warp = (kq 0..3, ghalf 0..1); thread = 4b x 4g ----
    const int lane  = tid & 31;
    const int wrp   = tid >> 5;
    const int kq    = wrp >> 1;
    const int ghalf = wrp & 1;
    const int bs    = (lane & 1) * 4;                     // b: bs..bs+3
    const int gi    = (lane >> 1) & 15;
    const int g0    = ghalf * 64 + gi * 4;                // g: g0..g0+3
    const int kp0   = kq * KQ;

    // ---- x prefetch (tid < 64): one u64 = 2 channels of one batch row ----
    const int xc = tid & 7, xb = tid >> 3;
    ull xp = 0;
    if (tid < 64)
        xp = __ldcg((const ull*)(g_xt) + (size_t)(b0 + xb) * 8 + xc);

    for (int s = 0; s < TT; ++s) {
        // ---- commit prefetched x_t; prefetch next step ----
        if (tid < 64) {
            ht[(128 + xc) * HT_P + xb] = xp;
            if (s + 1 < TT)
                xp = __ldcg((const ull*)(g_xt) + (size_t)(s + 1) * (BB * CC / 2) +
                            (size_t)(b0 + xb) * 8 + xc);
        }
        // ---- stage h_prev: 8 rows x 256 = 1024 u64, 4 per thread ----
        if (s == 0) {
#pragma unroll
            for (int i = 0; i < 4; ++i) {
                const int idx = i * NTHR + tid;
                ht[(idx & 127) * HT_P + (idx >> 7)] = 0ull;
            }
        } else {
            const ull* hsrc = (const ull*)g_h[s & 1] + (size_t)b0 * (HH / 2);
#pragma unroll
            for (int i = 0; i < 4; ++i) {
                const int idx = i * NTHR + tid;          // b*128 + kp (coalesced)
                const int b = idx >> 7, kp = idx & 127;
                ht[kp * HT_P + b] = __ldcg(hsrc + idx);
            }
        }
        __syncthreads();

        // ---- GEMM: 4b x 4g x 34 k-pairs, packed f32x2 ----
        ull a00=0,a01=0,a02=0,a03=0, a10=0,a11=0,a12=0,a13=0;
        ull a20=0,a21=0,a22=0,a23=0, a30=0,a31=0,a32=0,a33=0;
        const ull* hp = ht + kp0 * HT_P + bs;
        const ull* wr = wp + kp0 * WROW + g0;
#pragma unroll 2
        for (int kp = 0; kp < KQ; ++kp) {
            const ulonglong2 hA = *(const ulonglong2*)(hp);       // b: bs,bs+1
            const ulonglong2 hB = *(const ulonglong2*)(hp + 2);   // b: bs+2,bs+3
            const ulonglong2 wA = *(const ulonglong2*)(wr);       // g: g0,g0+1
            const ulonglong2 wB = *(const ulonglong2*)(wr + 2);   // g: g0+2,g0+3
            a00 = ffma2(hA.x, wA.x, a00); a01 = ffma2(hA.x, wA.y, a01);
            a02 = ffma2(hA.x, wB.x, a02); a03 = ffma2(hA.x, wB.y, a03);
            a10 = ffma2(hA.y, wA.x, a10); a11 = ffma2(hA.y, wA.y, a11);
            a12 = ffma2(hA.y, wB.x, a12); a13 = ffma2(hA.y, wB.y, a13);
            a20 = ffma2(hB.x, wA.x, a20); a21 = ffma2(hB.x, wA.y, a21);
            a22 = ffma2(hB.x, wB.x, a22); a23 = ffma2(hB.x, wB.y, a23);
            a30 = ffma2(hB.y, wA.x, a30); a31 = ffma2(hB.y, wA.y, a31);
            a32 = ffma2(hB.y, wB.x, a32); a33 = ffma2(hB.y, wB.y, a33);
            hp += HT_P;
            wr += WROW;
        }
        {
            float* gp = gpart + kq * 1024 + bs * 128 + g0;
            *(float4*)(gp)       = make_float4(psum(a00), psum(a01), psum(a02), psum(a03));
            *(float4*)(gp + 128) = make_float4(psum(a10), psum(a11), psum(a12), psum(a13));
            *(float4*)(gp + 256) = make_float4(psum(a20), psum(a21), psum(a22), psum(a23));
            *(float4*)(gp + 384) = make_float4(psum(a30), psum(a31), psum(a32), psum(a33));
        }
        __syncthreads();

        // ---- pointwise: one (b,u) cell per thread ----
        {
            const float* gp = gpart + pb * 128 + pu;
            float iv = bI, fv = bF, gv = bG, ov = bO;
#pragma unroll
            for (int k = 0; k < 4; ++k) {
                iv += gp[k * 1024];
                fv += gp[k * 1024 + 32];
                gv += gp[k * 1024 + 64];
                ov += gp[k * 1024 + 96];
            }
            cReg = sigf(fv) * cReg + sigf(iv) * tanhfa(gv);
            const float h = sigf(ov) * tanhfa(cReg);
            g_h[(s + 1) & 1][(size_t)(b0 + pb) * HH + u0 + pu] = h;
        }

        // ---- group barrier (8 blocks): release-atomic + direct counter poll ----
        __syncthreads();
        if (tid == 0) {
            unsigned* cnt = &g_cnt[bt * 32];
            unsigned old;
            asm volatile("atom.release.gpu.global.add.u32 %0, [%1], 1;"
                         : "=r"(old) : "l"(cnt) : "memory");
            if (old != (unsigned)(8 * (s + 1) - 1)) {
                unsigned v;
                do {
                    asm volatile("ld.acquire.gpu.global.u32 %0, [%1];"
                                 : "=r"(v) : "l"(cnt) : "memory");
                } while (v < (unsigned)(8 * (s + 1)));
            }
        }
        __syncthreads();
    }
}

// ---------------- classifier + log_softmax ----------------
__global__ void head_kernel(const float* __restrict__ w_out,
                            const float* __restrict__ b_out,
                            float* __restrict__ out)
{
    __shared__ float4 ws[NOUT][64];
    __shared__ float bsm[NOUT];
    const int tid = threadIdx.x;
    for (int q = tid; q < NOUT * 64; q += 128)
        ws[q / 64][q & 63] = ((const float4*)w_out)[q];
    if (tid < NOUT) bsm[tid] = b_out[tid];
    __syncthreads();

    const int b     = blockIdx.x * 16 + (tid >> 3);
    const int slice = tid & 7;
    const float4* hr4 = (const float4*)(g_h[0] + (size_t)b * HH) + slice * 8;

    float acc[NOUT];
#pragma unroll
    for (int j = 0; j < NOUT; ++j) acc[j] = 0.f;
#pragma unroll
    for (int k4 = 0; k4 < 8; ++k4) {
        const float4 hv = hr4[k4];
#pragma unroll
        for (int j = 0; j < NOUT; ++j) {
            const float4 wv = ws[j][slice * 8 + k4];
            acc[j] += hv.x * wv.x + hv.y * wv.y + hv.z * wv.z + hv.w * wv.w;
        }
    }
#pragma unroll
    for (int off = 4; off > 0; off >>= 1)
#pragma unroll
        for (int j = 0; j < NOUT; ++j)
            acc[j] += __shfl_down_sync(0xffffffffu, acc[j], off, 8);

    if (slice == 0) {
#pragma unroll
        for (int j = 0; j < NOUT; ++j) acc[j] += bsm[j];
        float m = acc[0];
#pragma unroll
        for (int j = 1; j < NOUT; ++j) m = fmaxf(m, acc[j]);
        float sum = 0.f;
#pragma unroll
        for (int j = 0; j < NOUT; ++j) sum += expf(acc[j] - m);
        const float lse = m + logf(sum);
#pragma unroll
        for (int j = 0; j < NOUT; ++j) out[b * NOUT + j] = acc[j] - lse;
    }
}

extern "C" void kernel_launch(void* const* d_in, const int* in_sizes, int n_in,
                              void* d_out, int out_size) {
    const float* x     = (const float*)d_in[0];
    const float* w_ih  = (const float*)d_in[1];
    const float* w_hh  = (const float*)d_in[2];
    const float* b_ih  = (const float*)d_in[3];
    const float* b_hh  = (const float*)d_in[4];
    const float* w_out = (const float*)d_in[5];
    const float* b_out = (const float*)d_in[6];
    float* out = (float*)d_out;

    cudaFuncSetAttribute(lstm_kernel, cudaFuncAttributeMaxDynamicSharedMemorySize, SMEM_BYTES);

    init_kernel<<<(BB * HH + 255) / 256, 256>>>();
    trans_kernel<<<dim3(TT / 32, (BB * CC) / 32), dim3(32, 8)>>>(x);
    lstm_kernel<<<128, NTHR, SMEM_BYTES>>>(w_ih, w_hh, b_ih, b_hh);
    head_kernel<<<8, 128>>>(w_out, b_out, out);
}

// round 15
// speedup vs baseline: 2.0056x; 1.0287x over previous
#include <cuda_runtime.h>
#include <cstdint>

#define BB    128
#define CC    16
#define TT    2048
#define HH    256
#define NOUT  10
#define NTHR  256
#define KP    136     // k-pairs: 128 (h) + 8 (x)
#define HT_P  10      // ht row pitch (ull), 16B-aligned rows
#define WROW  130     // W row pitch (ull)

#define WP_ULL  (KP * WROW)          // 17680
#define HT_ULL  (KP * HT_P)          // 1360
static const int SMEM_BYTES = (WP_ULL + HT_ULL) * 8 + 4096 * 4;  // 168704

typedef unsigned long long ull;

// ---- persistent device state ----
__device__ float g_xt[TT * BB * CC];           // x transposed to [t][b*c]
__device__ float g_h[2][BB * HH];              // h double buffer
__device__ unsigned g_cnt[16 * 32];            // per-group arrival counters (128B apart)

__device__ __forceinline__ ull ffma2(ull a, ull b, ull c) {
    ull d;
    asm("fma.rn.f32x2 %0, %1, %2, %3;" : "=l"(d) : "l"(a), "l"(b), "l"(c));
    return d;
}
__device__ __forceinline__ float psum(ull v) {
    return __uint_as_float((unsigned)(v & 0xffffffffu)) +
           __uint_as_float((unsigned)(v >> 32));
}
__device__ __forceinline__ float sigf(float x)  { return 1.f / (1.f + __expf(-x)); }
__device__ __forceinline__ float tanhfa(float x){ return 1.f - 2.f / (__expf(2.f * x) + 1.f); }

// ---------------- init: zero h buffer 0, reset barrier state ----------------
__global__ void init_kernel() {
    int i = blockIdx.x * blockDim.x + threadIdx.x;
    if (i < BB * HH) g_h[0][i] = 0.f;
    if (i < 16 * 32) g_cnt[i] = 0u;
}

// ---------------- transpose x: (b*c, T) -> (t, b*c) ----------------
__global__ void trans_kernel(const float* __restrict__ x) {
    __shared__ float tile[32][33];
    const int t0 = blockIdx.x * 32, r0 = blockIdx.y * 32;
    const int tx = threadIdx.x, ty = threadIdx.y;  // 32 x 8
#pragma unroll
    for (int i = 0; i < 32; i += 8)
        tile[ty + i][tx] = x[(size_t)(r0 + ty + i) * TT + t0 + tx];
    __syncthreads();
#pragma unroll
    for (int i = 0; i < 32; i += 8)
        g_xt[(size_t)(t0 + ty + i) * (BB * CC) + r0 + tx] = tile[tx][ty + i];
}

// ---------------- persistent LSTM: 16 groups x 8 blocks ----------------
__global__ void __launch_bounds__(NTHR, 1) lstm_kernel(
    const float* __restrict__ w_ih, const float* __restrict__ w_hh,
    const float* __restrict__ b_ih, const float* __restrict__ b_hh)
{
    extern __shared__ ull sm[];
    ull* wp = sm;                           // [KP][WROW] W tile (u64 chunks)
    ull* ht = sm + WP_ULL;                  // [KP][HT_P] k-paired [kp][b0..7]
    float* gpart = (float*)(ht + HT_ULL);   // [4 kq][8 b][128 g]

    const int tid = threadIdx.x;
    const int bt  = blockIdx.x >> 3;        // 16 batch tiles (sync group)
    const int ut  = blockIdx.x & 7;         // 8 unit tiles
    const int b0  = bt * 8;
    const int u0  = ut * 32;

    // ---- load W tile (once): local g in [0,128): grow = (g>>5)*HH + u0 + (g&31) ----
    for (int q = tid; q < KP * 128; q += NTHR) {
        const int kp = q >> 7, g = q & 127;
        const int grow = (g >> 5) * HH + u0 + (g & 31);
        ull v;
        if (kp < 128) v = *(const ull*)(w_hh + (size_t)grow * HH + 2 * kp);
        else          v = *(const ull*)(w_ih + (size_t)grow * CC + 2 * (kp - 128));
        wp[kp * WROW + g] = v;
    }

    // ---- pointwise thread state: (b,u) cell; biases in regs ----
    const int pb = tid >> 5;                // local batch 0..7
    const int pu = tid & 31;                // local unit 0..31
    float cReg = 0.f;
    const int ub = u0 + pu;
    const float bI = b_ih[ub]          + b_hh[ub];
    const float bF = b_ih[HH + ub]     + b_hh[HH + ub];
    const float bG = b_ih[2*HH + ub]   + b_hh[2*HH + ub];
    const float bO = b_ih[3*HH + ub]   + b_hh[3*HH + ub];

    // ---- GEMM mapping: warp = (kq 0..3, ghalf 0..1); thread = 4b x 4g ----
    const int lane  = tid & 31;
    const int wrp   = tid >> 5;
    const int kq    = wrp >> 1;
    const int ghalf = wrp & 1;
    const int bs    = (lane & 1) * 4;                     // b: bs..bs+3
    const int gi    = (lane >> 1) & 15;
    const int g0    = ghalf * 64 + gi * 4;                // g: g0..g0+3
    const int kh0   = kq * 32;                            // h k-range start
    const int kx0   = 128 + kq * 2;                       // x k-range start

    // ---- x prefetch (tid < 64): one u64 = 2 channels of one batch row ----
    const int xc = tid & 7, xb = tid >> 3;
    ull xp = 0;
    if (tid < 64)
        xp = __ldcg((const ull*)(g_xt) + (size_t)(b0 + xb) * 8 + xc);

    // staging indices (constant per thread)
    const int i0 = tid, i1 = NTHR + tid, i2 = 2 * NTHR + tid, i3 = 3 * NTHR + tid;

    for (int s = 0; s < TT; ++s) {
        // ---- issue h loads FIRST (in flight across x-commit + sync + x-GEMM) ----
        ull v0 = 0, v1 = 0, v2 = 0, v3 = 0;
        if (s > 0) {
            const ull* hsrc = (const ull*)g_h[s & 1] + (size_t)b0 * (HH / 2);
            v0 = __ldcg(hsrc + i0);
            v1 = __ldcg(hsrc + i1);
            v2 = __ldcg(hsrc + i2);
            v3 = __ldcg(hsrc + i3);
        }
        // ---- commit prefetched x_t; prefetch next step ----
        if (tid < 64) {
            ht[(128 + xc) * HT_P + xb] = xp;
            if (s + 1 < TT)
                xp = __ldcg((const ull*)(g_xt) + (size_t)(s + 1) * (BB * CC / 2) +
                            (size_t)(b0 + xb) * 8 + xc);
        }
        __syncthreads();   // x rows 128..135 visible

        // ---- accumulators ----
        ull a00=0,a01=0,a02=0,a03=0, a10=0,a11=0,a12=0,a13=0;
        ull a20=0,a21=0,a22=0,a23=0, a30=0,a31=0,a32=0,a33=0;

        // ---- x-GEMM: 2 k-pairs (compile-time) while h loads land ----
        {
            const ull* hp = ht + kx0 * HT_P + bs;
            const ull* wr = wp + kx0 * WROW + g0;
#pragma unroll
            for (int kp = 0; kp < 2; ++kp) {
                const ulonglong2 hA = *(const ulonglong2*)(hp);
                const ulonglong2 hB = *(const ulonglong2*)(hp + 2);
                const ulonglong2 wA = *(const ulonglong2*)(wr);
                const ulonglong2 wB = *(const ulonglong2*)(wr + 2);
                a00 = ffma2(hA.x, wA.x, a00); a01 = ffma2(hA.x, wA.y, a01);
                a02 = ffma2(hA.x, wB.x, a02); a03 = ffma2(hA.x, wB.y, a03);
                a10 = ffma2(hA.y, wA.x, a10); a11 = ffma2(hA.y, wA.y, a11);
                a12 = ffma2(hA.y, wB.x, a12); a13 = ffma2(hA.y, wB.y, a13);
                a20 = ffma2(hB.x, wA.x, a20); a21 = ffma2(hB.x, wA.y, a21);
                a22 = ffma2(hB.x, wB.x, a22); a23 = ffma2(hB.x, wB.y, a23);
                a30 = ffma2(hB.y, wA.x, a30); a31 = ffma2(hB.y, wA.y, a31);
                a32 = ffma2(hB.y, wB.x, a32); a33 = ffma2(hB.y, wB.y, a33);
                hp += HT_P;
                wr += WROW;
            }
        }

        // ---- commit landed h regs to ht (rows 0..127) ----
        ht[(i0 & 127) * HT_P + (i0 >> 7)] = v0;
        ht[(i1 & 127) * HT_P + (i1 >> 7)] = v1;
        ht[(i2 & 127) * HT_P + (i2 >> 7)] = v2;
        ht[(i3 & 127) * HT_P + (i3 >> 7)] = v3;
        __syncthreads();   // h rows visible

        // ---- h-GEMM: 32 k-pairs (compile-time) ----
        {
            const ull* hp = ht + kh0 * HT_P + bs;
            const ull* wr = wp + kh0 * WROW + g0;
#pragma unroll 2
            for (int kp = 0; kp < 32; ++kp) {
                const ulonglong2 hA = *(const ulonglong2*)(hp);
                const ulonglong2 hB = *(const ulonglong2*)(hp + 2);
                const ulonglong2 wA = *(const ulonglong2*)(wr);
                const ulonglong2 wB = *(const ulonglong2*)(wr + 2);
                a00 = ffma2(hA.x, wA.x, a00); a01 = ffma2(hA.x, wA.y, a01);
                a02 = ffma2(hA.x, wB.x, a02); a03 = ffma2(hA.x, wB.y, a03);
                a10 = ffma2(hA.y, wA.x, a10); a11 = ffma2(hA.y, wA.y, a11);
                a12 = ffma2(hA.y, wB.x, a12); a13 = ffma2(hA.y, wB.y, a13);
                a20 = ffma2(hB.x, wA.x, a20); a21 = ffma2(hB.x, wA.y, a21);
                a22 = ffma2(hB.x, wB.x, a22); a23 = ffma2(hB.x, wB.y, a23);
                a30 = ffma2(hB.y, wA.x, a30); a31 = ffma2(hB.y, wA.y, a31);
                a32 = ffma2(hB.y, wB.x, a32); a33 = ffma2(hB.y, wB.y, a33);
                hp += HT_P;
                wr += WROW;
            }
        }

        {
            float* gp = gpart + kq * 1024 + bs * 128 + g0;
            *(float4*)(gp)       = make_float4(psum(a00), psum(a01), psum(a02), psum(a03));
            *(float4*)(gp + 128) = make_float4(psum(a10), psum(a11), psum(a12), psum(a13));
            *(float4*)(gp + 256) = make_float4(psum(a20), psum(a21), psum(a22), psum(a23));
            *(float4*)(gp + 384) = make_float4(psum(a30), psum(a31), psum(a32), psum(a33));
        }
        __syncthreads();

        // ---- pointwise: one (b,u) cell per thread ----
        {
            const float* gp = gpart + pb * 128 + pu;
            float iv = bI, fv = bF, gv = bG, ov = bO;
#pragma unroll
            for (int k = 0; k < 4; ++k) {
                iv += gp[k * 1024];
                fv += gp[k * 1024 + 32];
                gv += gp[k * 1024 + 64];
                ov += gp[k * 1024 + 96];
            }
            cReg = sigf(fv) * cReg + sigf(iv) * tanhfa(gv);
            const float h = sigf(ov) * tanhfa(cReg);
            g_h[(s + 1) & 1][(size_t)(b0 + pb) * HH + u0 + pu] = h;
        }

        // ---- group barrier (8 blocks): release-atomic + direct counter poll ----
        __syncthreads();
        if (tid == 0) {
            unsigned* cnt = &g_cnt[bt * 32];
            unsigned old;
            asm volatile("atom.release.gpu.global.add.u32 %0, [%1], 1;"
                         : "=r"(old) : "l"(cnt) : "memory");
            if (old != (unsigned)(8 * (s + 1) - 1)) {
                unsigned v;
                do {
                    asm volatile("ld.acquire.gpu.global.u32 %0, [%1];"
                                 : "=r"(v) : "l"(cnt) : "memory");
                } while (v < (unsigned)(8 * (s + 1)));
            }
        }
        __syncthreads();
    }
}

// ---------------- classifier + log_softmax ----------------
__global__ void head_kernel(const float* __restrict__ w_out,
                            const float* __restrict__ b_out,
                            float* __restrict__ out)
{
    __shared__ float4 ws[NOUT][64];
    __shared__ float bsm[NOUT];
    const int tid = threadIdx.x;
    for (int q = tid; q < NOUT * 64; q += 128)
        ws[q / 64][q & 63] = ((const float4*)w_out)[q];
    if (tid < NOUT) bsm[tid] = b_out[tid];
    __syncthreads();

    const int b     = blockIdx.x * 16 + (tid >> 3);
    const int slice = tid & 7;
    const float4* hr4 = (const float4*)(g_h[0] + (size_t)b * HH) + slice * 8;

    float acc[NOUT];
#pragma unroll
    for (int j = 0; j < NOUT; ++j) acc[j] = 0.f;
#pragma unroll
    for (int k4 = 0; k4 < 8; ++k4) {
        const float4 hv = hr4[k4];
#pragma unroll
        for (int j = 0; j < NOUT; ++j) {
            const float4 wv = ws[j][slice * 8 + k4];
            acc[j] += hv.x * wv.x + hv.y * wv.y + hv.z * wv.z + hv.w * wv.w;
        }
    }
#pragma unroll
    for (int off = 4; off > 0; off >>= 1)
#pragma unroll
        for (int j = 0; j < NOUT; ++j)
            acc[j] += __shfl_down_sync(0xffffffffu, acc[j], off, 8);

    if (slice == 0) {
#pragma unroll
        for (int j = 0; j < NOUT; ++j) acc[j] += bsm[j];
        float m = acc[0];
#pragma unroll
        for (int j = 1; j < NOUT; ++j) m = fmaxf(m, acc[j]);
        float sum = 0.f;
#pragma unroll
        for (int j = 0; j < NOUT; ++j) sum += expf(acc[j] - m);
        const float lse = m + logf(sum);
#pragma unroll
        for (int j = 0; j < NOUT; ++j) out[b * NOUT + j] = acc[j] - lse;
    }
}

extern "C" void kernel_launch(void* const* d_in, const int* in_sizes, int n_in,
                              void* d_out, int out_size) {
    const float* x     = (const float*)d_in[0];
    const float* w_ih  = (const float*)d_in[1];
    const float* w_hh  = (const float*)d_in[2];
    const float* b_ih  = (const float*)d_in[3];
    const float* b_hh  = (const float*)d_in[4];
    const float* w_out = (const float*)d_in[5];
    const float* b_out = (const float*)d_in[6];
    float* out = (float*)d_out;

    cudaFuncSetAttribute(lstm_kernel, cudaFuncAttributeMaxDynamicSharedMemorySize, SMEM_BYTES);

    init_kernel<<<(BB * HH + 255) / 256, 256>>>();
    trans_kernel<<<dim3(TT / 32, (BB * CC) / 32), dim3(32, 8)>>>(x);
    lstm_kernel<<<128, NTHR, SMEM_BYTES>>>(w_ih, w_hh, b_ih, b_hh);
    head_kernel<<<8, 128>>>(w_out, b_out, out);
}